// round 2
// baseline (speedup 1.0000x reference)
#include <cuda_runtime.h>

#define B_ 4096
#define T_ 256
#define C_ 64
#define H_ 16
#define D_ 16
#define S_ 10

// Scratch: xw[b][t][h] = LN(cov) @ rnn_wx + rnn_b   (64 MB)
__device__ float g_xw[(long)B_ * T_ * H_];

// ---- fast transcendentals (MUFU-based, ~1e-6 accuracy) ----
__device__ __forceinline__ float fex2(float x) {
    float r; asm("ex2.approx.f32 %0, %1;" : "=f"(r) : "f"(x)); return r;
}
__device__ __forceinline__ float frcp(float x) {
    float r; asm("rcp.approx.f32 %0, %1;" : "=f"(r) : "f"(x)); return r;
}
__device__ __forceinline__ float fsig(float x) {
    // 1/(1+2^(-x*log2e))
    return frcp(1.0f + fex2(-1.4426950408889634f * x));
}
__device__ __forceinline__ float ftanh(float x) {
    // 2/(1+2^(-2x*log2e)) - 1
    return fmaf(2.0f, frcp(1.0f + fex2(-2.8853900817779268f * x)), -1.0f);
}

// ---- f32x2 packed FMA helpers ----
__device__ __forceinline__ unsigned long long pack2(float lo, float hi) {
    unsigned long long r;
    asm("mov.b64 %0, {%1, %2};" : "=l"(r) : "f"(lo), "f"(hi));
    return r;
}
__device__ __forceinline__ void unpack2(unsigned long long v, float& lo, float& hi) {
    asm("mov.b64 {%0, %1}, %2;" : "=f"(lo), "=f"(hi) : "l"(v));
}
__device__ __forceinline__ unsigned long long fma2(unsigned long long a,
                                                   unsigned long long b,
                                                   unsigned long long c) {
    unsigned long long r;
    asm("fma.rn.f32x2 %0, %1, %2, %3;" : "=l"(r) : "l"(a), "l"(b), "l"(c));
    return r;
}

// ---------------------------------------------------------------------------
// Kernel 1: fused LayerNorm + x @ Wx + b, LN folded into post-scaling.
//   xw_j = rs * (cov . Wg_:,j) - rs*mu*S1_j + S2_j
// One thread per (b,t) row; inner product via packed f32x2 FFMA2.
// ---------------------------------------------------------------------------
__global__ void __launch_bounds__(256) k_ln_xw(
    const float* __restrict__ cov,
    const float* __restrict__ gamma,
    const float* __restrict__ beta,
    const float* __restrict__ wx,
    const float* __restrict__ rnn_b)
{
    __shared__ __align__(16) float sWg[C_ * H_];
    __shared__ float sS1[H_];
    __shared__ float sS2[H_];

    int tid = threadIdx.x;
    for (int i = tid; i < C_ * H_; i += blockDim.x) {
        int c = i >> 4;
        sWg[i] = gamma[c] * wx[i];
    }
    __syncthreads();
    if (tid < H_) {
        float s1 = 0.f, s2 = 0.f;
        for (int c = 0; c < C_; c++) {
            s1 += sWg[c * H_ + tid];
            s2 += beta[c] * wx[c * H_ + tid];
        }
        sS1[tid] = s1;
        sS2[tid] = s2 + rnn_b[tid];
    }
    __syncthreads();

    const ulonglong2* wg2 = reinterpret_cast<const ulonglong2*>(sWg);

    long r = (long)blockIdx.x * blockDim.x + tid;   // row = b*T + t
    if (r >= (long)B_ * T_) return;

    const float4* cv = reinterpret_cast<const float4*>(cov + r * C_);

    unsigned long long acc2[8];
#pragma unroll
    for (int m = 0; m < 8; m++) acc2[m] = pack2(0.f, 0.f);
    float sum = 0.f, sq = 0.f;

#pragma unroll
    for (int c4 = 0; c4 < C_ / 4; c4++) {
        float4 v = cv[c4];
        float xs[4] = {v.x, v.y, v.z, v.w};
#pragma unroll
        for (int k = 0; k < 4; k++) {
            float xc = xs[k];
            sum += xc;
            sq = fmaf(xc, xc, sq);
            unsigned long long xx = pack2(xc, xc);
            int c = c4 * 4 + k;
            ulonglong2 wA = wg2[c * 4 + 0];   // w[0..3]
            ulonglong2 wB = wg2[c * 4 + 1];   // w[4..7]
            ulonglong2 wC = wg2[c * 4 + 2];   // w[8..11]
            ulonglong2 wD = wg2[c * 4 + 3];   // w[12..15]
            acc2[0] = fma2(xx, wA.x, acc2[0]);
            acc2[1] = fma2(xx, wA.y, acc2[1]);
            acc2[2] = fma2(xx, wB.x, acc2[2]);
            acc2[3] = fma2(xx, wB.y, acc2[3]);
            acc2[4] = fma2(xx, wC.x, acc2[4]);
            acc2[5] = fma2(xx, wC.y, acc2[5]);
            acc2[6] = fma2(xx, wD.x, acc2[6]);
            acc2[7] = fma2(xx, wD.y, acc2[7]);
        }
    }

    float mu  = sum * (1.0f / 64.0f);
    float var = sq  * (1.0f / 64.0f) - mu * mu;
    float rs  = rsqrtf(var + 1e-3f);
    float rm  = rs * mu;

    float4 o[4];
    float* op = reinterpret_cast<float*>(o);
#pragma unroll
    for (int m = 0; m < 8; m++) {
        float a0, a1;
        unpack2(acc2[m], a0, a1);
        int j = m * 2;
        op[j]     = rs * a0 - rm * sS1[j]     + sS2[j];
        op[j + 1] = rs * a1 - rm * sS1[j + 1] + sS2[j + 1];
    }

    float4* outp = reinterpret_cast<float4*>(g_xw + r * H_);
    outp[0] = o[0]; outp[1] = o[1]; outp[2] = o[2]; outp[3] = o[3];
}

// ---------------------------------------------------------------------------
// Kernel 2: sequential scan over T. 16-lane teams, 2 teams/warp, and each
// thread carries TWO batch slots (4 independent chains per warp) for latency
// hiding. xw for t+1 is prefetched during step t.
// ---------------------------------------------------------------------------
__global__ void __launch_bounds__(64) k_scan(
    const float* __restrict__ states_seq,
    const float* __restrict__ wh,
    const float* __restrict__ d1w,
    const float* __restrict__ d1b,
    const float* __restrict__ d2w,
    const float* __restrict__ d2b,
    float* __restrict__ out)
{
    const unsigned FULL = 0xffffffffu;
    int tid = threadIdx.x;       // 0..63
    int q = tid & 15;
    int team = tid >> 4;         // 0..3

    int bb[2];
    bb[0] = blockIdx.x * 8 + team;       // slot 0
    bb[1] = bb[0] + 4;                   // slot 1

    // Weight columns (column q of each matrix)
    float whc[H_], d1c[H_], d2c[H_];
#pragma unroll
    for (int i = 0; i < H_; i++) {
        whc[i] = wh[i * H_ + q];
        d1c[i] = d1w[i * H_ + q];
        d2c[i] = d2w[i * D_ + q];
    }
    float b1q = d1b[q], b2q = d2b[q];

    // Per-lane driver transform params: tv = sig(argscale*d)*mul + add
    float mul = 1.0f, add = 0.0f;
    if      (q == 0) { mul = 0.4f;  add = -0.2f; }
    else if (q == 2) { mul = 0.5f;  }
    else if (q == 3) { mul = 0.1f;  }
    else if (q == 4) { mul = 0.2f;  }
    else if (q == 8) { mul = 0.35f; }
    else if (q == 9) { mul = 0.1f;  }
    float argscale = (q == 0) ? 2.0f : 1.0f;

    // Cash-budget state, replicated across team lanes, one copy per slot
    float rev[2], cash[2], ar[2], inv[2], ppe[2], ap[2], debt[2], eqty[2], re[2], oth[2];
    const float* xwp[2];
    float* sto[2];
    float* iso[2];
#pragma unroll
    for (int s = 0; s < 2; s++) {
        const float* s0 = states_seq + (long)bb[s] * T_ * S_;
        rev[s] = s0[0]; cash[s] = s0[1]; ar[s] = s0[2]; inv[s] = s0[3]; ppe[s] = s0[4];
        ap[s]  = s0[5]; debt[s] = s0[6]; eqty[s] = s0[7]; re[s] = s0[8]; oth[s] = s0[9];
        xwp[s] = g_xw + (long)bb[s] * T_ * H_;
        sto[s] = out + (long)bb[s] * (T_ - 1) * S_;
        iso[s] = out + (long)B_ * (T_ - 1) * S_ + (long)bb[s] * (T_ - 1) * 7;
    }

    float h[2] = {0.f, 0.f};
    float xwc[2];
#pragma unroll
    for (int s = 0; s < 2; s++) xwc[s] = xwp[s][q];   // t = 0

    for (int t = 0; t < T_; t++) {
        // prefetch next step's xw (hides L2/DRAM latency off the chain)
        float xwn[2] = {0.f, 0.f};
        if (t + 1 < T_) {
#pragma unroll
            for (int s = 0; s < 2; s++) xwn[s] = xwp[s][(t + 1) * H_ + q];
        }

        // RNN step: h = tanh(xw_t + h @ Wh), split accumulators for ILP
#pragma unroll
        for (int s = 0; s < 2; s++) {
            float a0 = xwc[s], a1 = 0.f;
#pragma unroll
            for (int i = 0; i < H_; i += 2) {
                a0 = fmaf(__shfl_sync(FULL, h[s], i,     16), whc[i],     a0);
                a1 = fmaf(__shfl_sync(FULL, h[s], i + 1, 16), whc[i + 1], a1);
            }
            h[s] = ftanh(a0 + a1);
        }

        if (t >= 1) {
            float a[2], dd[2];
#pragma unroll
            for (int s = 0; s < 2; s++) {
                float a0 = b1q, a1 = 0.f;
#pragma unroll
                for (int i = 0; i < H_; i += 2) {
                    a0 = fmaf(__shfl_sync(FULL, h[s], i,     16), d1c[i],     a0);
                    a1 = fmaf(__shfl_sync(FULL, h[s], i + 1, 16), d1c[i + 1], a1);
                }
                a[s] = ftanh(a0 + a1);
            }
#pragma unroll
            for (int s = 0; s < 2; s++) {
                float a0 = b2q, a1 = 0.f;
#pragma unroll
                for (int i = 0; i < H_; i += 2) {
                    a0 = fmaf(__shfl_sync(FULL, a[s], i,     16), d2c[i],     a0);
                    a1 = fmaf(__shfl_sync(FULL, a[s], i + 1, 16), d2c[i + 1], a1);
                }
                dd[s] = a0 + a1;
            }

#pragma unroll
            for (int s = 0; s < 2; s++) {
                // distributed transform, then broadcast
                float tv = fsig(argscale * dd[s]) * mul + add;
                float tr0 = __shfl_sync(FULL, tv, 0, 16);
                float tr1 = __shfl_sync(FULL, tv, 1, 16);
                float tr2 = __shfl_sync(FULL, tv, 2, 16);
                float tr3 = __shfl_sync(FULL, tv, 3, 16);
                float tr4 = __shfl_sync(FULL, tv, 4, 16);
                float tr5 = __shfl_sync(FULL, tv, 5, 16);
                float tr6 = __shfl_sync(FULL, tv, 6, 16);
                float tr7 = __shfl_sync(FULL, tv, 7, 16);
                float tr8 = __shfl_sync(FULL, tv, 8, 16);
                float tr9 = __shfl_sync(FULL, tv, 9, 16);

                float nrev  = rev[s] * (1.0f + tr0);
                float cogs  = tr1 * nrev;
                float opex  = tr2 * nrev;
                float dep   = tr3 * ppe[s];
                float intr  = tr9 * debt[s];
                float ebt   = nrev - cogs - opex - dep - intr;
                float tax   = tr8 * fmaxf(ebt, 0.0f);
                float ni    = ebt - tax;
                float arn   = tr5 * nrev;
                float invn  = tr6 * cogs;
                float apn   = tr7 * cogs;
                float capex = tr4 * nrev;
                float ppen  = ppe[s] + capex - dep;
                float cashn = cash[s] + ni + dep - capex - (arn - ar[s]) - (invn - inv[s]) + (apn - ap[s]);
                float ren   = re[s] + ni;

                int o = t - 1;
                float sv = nrev;
                if      (q == 1) sv = cashn;
                else if (q == 2) sv = arn;
                else if (q == 3) sv = invn;
                else if (q == 4) sv = ppen;
                else if (q == 5) sv = apn;
                else if (q == 6) sv = debt[s];
                else if (q == 7) sv = eqty[s];
                else if (q == 8) sv = ren;
                else if (q == 9) sv = oth[s];
                if (q < S_) sto[s][o * S_ + q] = sv;

                float iv = nrev;
                if      (q == 1) iv = cogs;
                else if (q == 2) iv = opex;
                else if (q == 3) iv = dep;
                else if (q == 4) iv = intr;
                else if (q == 5) iv = tax;
                else if (q == 6) iv = ni;
                if (q < 7) iso[s][o * 7 + q] = iv;

                rev[s] = nrev; cash[s] = cashn; ar[s] = arn; inv[s] = invn;
                ppe[s] = ppen; ap[s] = apn; re[s] = ren;
            }
        }
#pragma unroll
        for (int s = 0; s < 2; s++) xwc[s] = xwn[s];
    }
}

extern "C" void kernel_launch(void* const* d_in, const int* in_sizes, int n_in,
                              void* d_out, int out_size)
{
    const float* states = (const float*)d_in[0];
    const float* cov    = (const float*)d_in[1];
    const float* gamma  = (const float*)d_in[2];
    const float* beta   = (const float*)d_in[3];
    const float* wx     = (const float*)d_in[4];
    const float* wh     = (const float*)d_in[5];
    const float* rnn_b  = (const float*)d_in[6];
    const float* d1w    = (const float*)d_in[7];
    const float* d1b    = (const float*)d_in[8];
    const float* d2w    = (const float*)d_in[9];
    const float* d2b    = (const float*)d_in[10];
    float* out = (float*)d_out;

    k_ln_xw<<<(B_ * T_) / 256, 256>>>(cov, gamma, beta, wx, rnn_b);
    k_scan<<<B_ / 8, 64>>>(states, wh, d1w, d1b, d2w, d2b, out);
}